// round 16
// baseline (speedup 1.0000x reference)
#include <cuda_runtime.h>
#include <cuda_fp16.h>
#include <cstdint>
#include <math.h>

#define FILTER_LEN 1024
#define HOP        512
#define CUTOFF     513
#define BATCH      8
#define TLEN       1048576
#define NFRAMES    2049
#define NGEMM      2048
#define KH         512                     // halved K via DFT symmetry
#define FH         512                     // freqs handled by GEMM (f<512)

#define BM      128
#define BN      128
#define KC      64                         // fp16 k per chunk (128 B rows)
#define NITER   16                         // 8 R-chunks + 8 I-chunks

// stage: A(128 rows x 128B) + B(128 rows x 128B); 3 stages
#define SA      0
#define SB      16384
#define STAGE   32768
#define NSTAGE  3
#define DSMEM   (NSTAGE * STAGE)           // 96 KB -> 2 CTAs/SM

#define NGEMM_CTAS 512                     // 16 n x 4 m x 8 b
#define NREM_CTAS  80                      // 512+80 = 592 = 2 x 296 slots
#define NREM    (BATCH * (NFRAMES + 512))  // 20488 outputs
#define REMW    (NREM_CTAS * 8)            // 640 remainder warps

// ---------------- device scratch -------------------------------------------
__device__ __align__(128) __half g_E [(size_t)BATCH * NGEMM * KH];
__device__ __align__(128) __half g_O [(size_t)BATCH * NGEMM * KH];
__device__ __align__(128) __half g_AE[(size_t)FH * KH];
__device__ __align__(128) __half g_AO[(size_t)FH * KH];
__device__ __align__(128) float  g_R [(size_t)BATCH * FH * NGEMM];

// ---------------- helpers ---------------------------------------------------
__device__ __forceinline__ uint32_t smem_u32(const void* p) {
    uint32_t a;
    asm("{ .reg .u64 t; cvta.to.shared.u64 t, %1; cvt.u32.u64 %0, t; }"
        : "=r"(a) : "l"(p));
    return a;
}
__device__ __forceinline__ void cp_async16(uint32_t dst, const void* src) {
    asm volatile("cp.async.cg.shared.global [%0], [%1], 16;"
                 :: "r"(dst), "l"(src) : "memory");
}
__device__ __forceinline__ void cp_commit() {
    asm volatile("cp.async.commit_group;" ::: "memory");
}
template <int N> __device__ __forceinline__ void cp_wait() {
    asm volatile("cp.async.wait_group %0;" :: "n"(N) : "memory");
}
__device__ __forceinline__ void ldsm_x4(uint32_t& r0, uint32_t& r1,
                                        uint32_t& r2, uint32_t& r3, uint32_t addr) {
    asm volatile("ldmatrix.sync.aligned.m8n8.x4.shared.b16 {%0,%1,%2,%3}, [%4];"
                 : "=r"(r0), "=r"(r1), "=r"(r2), "=r"(r3) : "r"(addr));
}
__device__ __forceinline__ void mma_f16(float* d, const uint32_t* a,
                                        uint32_t b0, uint32_t b1) {
    asm volatile(
        "mma.sync.aligned.m16n8k16.row.col.f32.f16.f16.f32 "
        "{%0,%1,%2,%3}, {%4,%5,%6,%7}, {%8,%9}, {%0,%1,%2,%3};"
        : "+f"(d[0]), "+f"(d[1]), "+f"(d[2]), "+f"(d[3])
        : "r"(a[0]), "r"(a[1]), "r"(a[2]), "r"(a[3]), "r"(b0), "r"(b1));
}
__device__ __forceinline__ uint32_t packh2(float a, float b) {
    __half2 t = __floats2half2_rn(a, b);
    return *reinterpret_cast<uint32_t*>(&t);
}
__device__ __forceinline__ int reflect_idx(int j) {
    if (j < 0) j = -j;
    else if (j >= TLEN) j = 2 * TLEN - 2 - j;
    return j;
}

// ---------------- prep 1: E/O construction (float4 fast path) ---------------
__global__ void eo_kernel(const float* __restrict__ x) {
    size_t v = (size_t)blockIdx.x * blockDim.x + threadIdx.x;   // 8-j group
    const size_t total = (size_t)BATCH * NGEMM * (KH / 8);
    if (v >= total) return;
    const int jg = (int)(v % (KH / 8));
    const int n  = (int)((v / (KH / 8)) % NGEMM);
    const int b  = (int)(v / ((size_t)(KH / 8) * NGEMM));
    const float* xb = x + (size_t)b * TLEN;
    const int j0 = jg * 8;

    float e[8], o[8];
    if (n >= 1 && n <= 2046) {
        const float* asc = xb + (size_t)n * HOP - 512 + j0;
        const float4 a0 = *reinterpret_cast<const float4*>(asc);
        const float4 a1 = *reinterpret_cast<const float4*>(asc + 4);
        const int C = n * HOP + 512 - j0;
        const float4 d0 = *reinterpret_cast<const float4*>(xb + C - 8);
        const float4 d1 = *reinterpret_cast<const float4*>(xb + C - 4);
        const float xC = xb[C];
        const float x1[8] = { a0.x, a0.y, a0.z, a0.w, a1.x, a1.y, a1.z, a1.w };
        const float x2[8] = { xC, d1.w, d1.z, d1.y, d1.x, d0.w, d0.z, d0.y };
        #pragma unroll
        for (int t = 0; t < 8; ++t) {
            e[t] = x1[t] + x2[t];
            o[t] = x1[t] - x2[t];
        }
    } else {
        #pragma unroll
        for (int t = 0; t < 8; ++t) {
            const int j = j0 + t;
            const float x1 = xb[reflect_idx(n * HOP + j - 512)];
            const float x2 = xb[reflect_idx(n * HOP + 512 - j)];
            e[t] = x1 + x2;
            o[t] = x1 - x2;
        }
    }
    if (jg == 0) { e[0] = xb[reflect_idx(n * HOP)]; o[0] = 0.f; }
    const size_t base = ((size_t)b * NGEMM + n) * KH + j0;
    *reinterpret_cast<uint4*>(g_E + base) =
        make_uint4(packh2(e[0], e[1]), packh2(e[2], e[3]),
                   packh2(e[4], e[5]), packh2(e[6], e[7]));
    *reinterpret_cast<uint4*>(g_O + base) =
        make_uint4(packh2(o[0], o[1]), packh2(o[2], o[3]),
                   packh2(o[4], o[5]), packh2(o[6], o[7]));
}

// ---------------- prep 2: basis halves (split into 2 launches) --------------
__global__ void basis_eo_kernel(const float* __restrict__ basis, int f0) {
    size_t v = (size_t)blockIdx.x * blockDim.x + threadIdx.x;   // 8-j group
    if (v >= (size_t)(FH / 2) * (KH / 8)) return;
    const int jg = (int)(v % (KH / 8));
    const int f  = f0 + (int)(v / (KH / 8));
    const int j0 = jg * 8;
    const float* bR = basis + (size_t)f * FILTER_LEN;
    const float* bI = basis + (size_t)(CUTOFF + f) * FILTER_LEN;
    float ae[8], ao[8];
    #pragma unroll
    for (int t = 0; t < 8; ++t) {
        const int j = j0 + t;
        if (j == 0) {
            ae[t] = bR[512];
            ao[t] = 0.f;
        } else {
            ae[t] = 0.5f * (bR[j] + bR[FILTER_LEN - j]);
            ao[t] = 0.5f * (bI[j] - bI[FILTER_LEN - j]);
        }
    }
    const size_t base = (size_t)f * KH + j0;
    *reinterpret_cast<uint4*>(g_AE + base) =
        make_uint4(packh2(ae[0], ae[1]), packh2(ae[2], ae[3]),
                   packh2(ae[4], ae[5]), packh2(ae[6], ae[7]));
    *reinterpret_cast<uint4*>(g_AO + base) =
        make_uint4(packh2(ao[0], ao[1]), packh2(ao[2], ao[3]),
                   packh2(ao[4], ao[5]), packh2(ao[6], ao[7]));
}

// ---------------- main: 592-CTA packed (512 GEMM + 80 remainder) ------------
__global__ __launch_bounds__(256, 2)
void stft_mma_kernel(const float* __restrict__ x,
                     const float* __restrict__ basis,
                     const float* __restrict__ eps_p,
                     float* __restrict__ out)
{
    const int tid  = threadIdx.x;
    const int wid  = tid >> 5;
    const int lane = tid & 31;
    const int bid  = (int)blockIdx.x;

    // ======== remainder CTAs (bid >= 512): f=512 row + n=2048 col ==========
    if (bid >= NGEMM_CTAS) {
        const float eps = *eps_p;
        const int wbase = (bid - NGEMM_CTAS) * 8 + wid;
        for (int o = wbase; o < NREM; o += REMW) {
            const int b = o / (NFRAMES + 512);
            const int r = o % (NFRAMES + 512);
            int f, n;
            if (r < NFRAMES) { f = 512; n = r; }
            else             { f = r - NFRAMES; n = 2048; }
            const float* bR = basis + (size_t)f * FILTER_LEN;
            const float* bI = basis + (size_t)(f + CUTOFF) * FILTER_LEN;
            const float* xb = x + (size_t)b * TLEN;
            float aR = 0.f, aI = 0.f;
            #pragma unroll 4
            for (int k = lane; k < FILTER_LEN; k += 32) {
                const int j = reflect_idx(n * HOP + k - 512);
                const float xv = xb[j];
                aR = fmaf(bR[k], xv, aR);
                aI = fmaf(bI[k], xv, aI);
            }
            #pragma unroll
            for (int s = 16; s; s >>= 1) {
                aR += __shfl_xor_sync(0xffffffffu, aR, s);
                aI += __shfl_xor_sync(0xffffffffu, aI, s);
            }
            if (lane == 0)
                out[((size_t)b * CUTOFF + f) * NFRAMES + n] =
                    sqrtf(fmaf(aR, aR, fmaf(aI, aI, eps)));
        }
        return;
    }

    // ======== dense fp16 GEMM: 128f x 128n, warp 32x64, R-phase + I-phase ==
    extern __shared__ char dsm[];
    const uint32_t sbase = smem_u32(dsm);

    const int n0 = (bid & 15) * BN;        // 16 n-tiles
    const int m0 = ((bid >> 4) & 3) * BM;  // 4 m-tiles
    const int b  = bid >> 6;               // 8 batches

    const int warp_m = (wid >> 1) * 32;    // 0,32,64,96
    const int warp_n = (wid & 1) * 64;     // 0,64

    // loader: A/B each 1024 16B chunks -> 4 rounds of 256 threads
    int l_row[4], l_c16[4]; uint32_t l_soff[4];
    #pragma unroll
    for (int j = 0; j < 4; ++j) {
        int chunk = tid + j * 256;
        l_row[j] = chunk >> 3;
        l_c16[j] = chunk & 7;
        l_soff[j] = (uint32_t)l_row[j] * 128 + (uint32_t)((l_c16[j] ^ (l_row[j] & 7)) * 16);
    }

    const __half* aE = g_AE + (size_t)m0 * KH;
    const __half* aO = g_AO + (size_t)m0 * KH;
    const __half* bE = g_E + ((size_t)b * NGEMM + n0) * KH;
    const __half* bO = g_O + ((size_t)b * NGEMM + n0) * KH;
    float* dst = g_R + ((size_t)b * FH + m0) * NGEMM + n0;

    float acc[2][8][4];
    #pragma unroll
    for (int mt = 0; mt < 2; ++mt)
        #pragma unroll
        for (int nt = 0; nt < 8; ++nt)
            #pragma unroll
            for (int r = 0; r < 4; ++r) acc[mt][nt][r] = 0.f;

    const int lm_r = lane & 15;
    const int lm_s = lane >> 4;
    const int r4 = lane >> 2;
    const int c2 = (lane & 3) * 2;

    auto load_stage = [&](int i) {
        const uint32_t st = sbase + (uint32_t)(i % NSTAGE) * STAGE;
        const __half* ap = (i < 8) ? aE : aO;
        const __half* bp = (i < 8) ? bE : bO;
        const int k0 = (i & 7) * KC;
        #pragma unroll
        for (int j = 0; j < 4; ++j) {
            cp_async16(st + SA + l_soff[j],
                       ap + (size_t)l_row[j] * KH + k0 + l_c16[j] * 8);
            cp_async16(st + SB + l_soff[j],
                       bp + (size_t)l_row[j] * KH + k0 + l_c16[j] * 8);
        }
        cp_commit();
    };

    load_stage(0);
    load_stage(1);

    for (int i = 0; i < NITER; ++i) {
        if (i + 1 < NITER) cp_wait<1>(); else cp_wait<0>();
        __syncthreads();                    // stage i ready
        if (i + 2 < NITER) load_stage(i + 2);

        if (i == 8) {
            // R phase complete: dump accs to scratch, reset for I phase
            #pragma unroll
            for (int mt = 0; mt < 2; ++mt) {
                const int fl = warp_m + mt * 16 + r4;
                #pragma unroll
                for (int nt = 0; nt < 8; ++nt) {
                    const int nl = warp_n + nt * 8 + c2;
                    *reinterpret_cast<float2*>(dst + (size_t)fl * NGEMM + nl) =
                        make_float2(acc[mt][nt][0], acc[mt][nt][1]);
                    *reinterpret_cast<float2*>(dst + (size_t)(fl + 8) * NGEMM + nl) =
                        make_float2(acc[mt][nt][2], acc[mt][nt][3]);
                    acc[mt][nt][0] = 0.f; acc[mt][nt][1] = 0.f;
                    acc[mt][nt][2] = 0.f; acc[mt][nt][3] = 0.f;
                }
            }
        }

        const uint32_t st = sbase + (uint32_t)(i % NSTAGE) * STAGE;

        #pragma unroll
        for (int ks = 0; ks < 4; ++ks) {
            const int c16 = ks * 2 + lm_s;
            uint32_t aF[2][4];
            #pragma unroll
            for (int mt = 0; mt < 2; ++mt) {
                const int row = warp_m + mt * 16 + lm_r;
                const uint32_t ad = st + SA + (uint32_t)row * 128
                                  + (uint32_t)((c16 ^ (row & 7)) * 16);
                ldsm_x4(aF[mt][0], aF[mt][1], aF[mt][2], aF[mt][3], ad);
            }
            #pragma unroll
            for (int g = 0; g < 4; ++g) {
                const int row = warp_n + g * 16 + lm_r;
                const uint32_t bd = st + SB + (uint32_t)row * 128
                                  + (uint32_t)((c16 ^ (row & 7)) * 16);
                uint32_t bf[4];
                ldsm_x4(bf[0], bf[1], bf[2], bf[3], bd);
                #pragma unroll
                for (int sub = 0; sub < 2; ++sub) {
                    const int nt = g * 2 + sub;
                    const uint32_t b0 = sub ? bf[1] : bf[0];
                    const uint32_t b1 = sub ? bf[3] : bf[2];
                    #pragma unroll
                    for (int mt = 0; mt < 2; ++mt)
                        mma_f16(acc[mt][nt], aF[mt], b0, b1);
                }
            }
        }
    }

    // ---- epilogue: read back R tile, combine with I accs, magnitude -------
    const float eps = *eps_p;
    #pragma unroll
    for (int mt = 0; mt < 2; ++mt) {
        #pragma unroll
        for (int nt = 0; nt < 8; ++nt) {
            const int fl = warp_m + mt * 16 + r4;
            const int nl = warp_n + nt * 8 + c2;
            const float2 r01 = *reinterpret_cast<const float2*>(
                dst + (size_t)fl * NGEMM + nl);
            const float2 r23 = *reinterpret_cast<const float2*>(
                dst + (size_t)(fl + 8) * NGEMM + nl);
            const int n = n0 + nl;
            float* o0 = out + ((size_t)b * CUTOFF + m0 + fl) * NFRAMES + n;
            float* o1 = out + ((size_t)b * CUTOFF + m0 + fl + 8) * NFRAMES + n;
            const float i0 = acc[mt][nt][0], i1 = acc[mt][nt][1];
            const float i2 = acc[mt][nt][2], i3 = acc[mt][nt][3];
            o0[0] = sqrtf(fmaf(r01.x, r01.x, fmaf(i0, i0, eps)));
            o0[1] = sqrtf(fmaf(r01.y, r01.y, fmaf(i1, i1, eps)));
            o1[0] = sqrtf(fmaf(r23.x, r23.x, fmaf(i2, i2, eps)));
            o1[1] = sqrtf(fmaf(r23.y, r23.y, fmaf(i3, i3, eps)));
        }
    }
}

// ---------------- launch ----------------------------------------------------
extern "C" void kernel_launch(void* const* d_in, const int* in_sizes, int n_in,
                              void* d_out, int out_size)
{
    const float* x     = (const float*)d_in[0];
    const float* basis = (const float*)d_in[1];
    const float* eps   = (const float*)d_in[2];
    float* out = (float*)d_out;

    {   // launch 1
        size_t tot = (size_t)BATCH * NGEMM * (KH / 8);
        eo_kernel<<<(unsigned)((tot + 255) / 256), 256>>>(x);
    }
    {   // launches 2+3 (keeps GEMM as launch #4 for ncu)
        size_t tot = (size_t)(FH / 2) * (KH / 8);
        basis_eo_kernel<<<(unsigned)((tot + 255) / 256), 256>>>(basis, 0);
        basis_eo_kernel<<<(unsigned)((tot + 255) / 256), 256>>>(basis, FH / 2);
    }
    {   // launch 4: 592 CTAs = exactly 2 waves at 2 CTAs/SM
        cudaFuncSetAttribute(stft_mma_kernel,
                             cudaFuncAttributeMaxDynamicSharedMemorySize, DSMEM);
        stft_mma_kernel<<<NGEMM_CTAS + NREM_CTAS, 256, DSMEM>>>(x, basis, eps, out);
    }
}

// round 17
// speedup vs baseline: 1.5783x; 1.5783x over previous
#include <cuda_runtime.h>
#include <cuda_fp16.h>
#include <cstdint>
#include <math.h>

#define FILTER_LEN 1024
#define HOP        512
#define CUTOFF     513
#define BATCH      8
#define TLEN       1048576
#define NFRAMES    2049
#define NGEMM      2048
#define KH         512                     // halved K via DFT symmetry
#define FH         512                     // freqs handled by GEMM (f<512)

#define BM      128
#define BN      128
#define KC      64                         // fp16 k per chunk (128 B rows)
#define NITER   16                         // 8 R-chunks + 8 I-chunks

// stage: A(128 rows x 128B) + B(128 rows x 128B); 3 stages
#define SA      0
#define SB      16384
#define STAGE   32768
#define NSTAGE  3
#define DSMEM   (NSTAGE * STAGE)           // 96 KB -> 2 CTAs/SM

#define NGEMM_CTAS 256                     // persistent: 2 tiles each (512 tiles)
#define NREM_CTAS  40                      // 256+40 = 296 = exactly all slots
#define NREM    (BATCH * (NFRAMES + 512))  // 20488 outputs
#define REMW    (NREM_CTAS * 8)            // 320 remainder warps

// ---------------- device scratch -------------------------------------------
__device__ __align__(128) __half g_E [(size_t)BATCH * NGEMM * KH];
__device__ __align__(128) __half g_O [(size_t)BATCH * NGEMM * KH];
__device__ __align__(128) __half g_AE[(size_t)FH * KH];
__device__ __align__(128) __half g_AO[(size_t)FH * KH];
__device__ __align__(128) float  g_R [(size_t)BATCH * FH * NGEMM];

// ---------------- helpers ---------------------------------------------------
__device__ __forceinline__ uint32_t smem_u32(const void* p) {
    uint32_t a;
    asm("{ .reg .u64 t; cvta.to.shared.u64 t, %1; cvt.u32.u64 %0, t; }"
        : "=r"(a) : "l"(p));
    return a;
}
__device__ __forceinline__ void cp_async16(uint32_t dst, const void* src) {
    asm volatile("cp.async.cg.shared.global [%0], [%1], 16;"
                 :: "r"(dst), "l"(src) : "memory");
}
__device__ __forceinline__ void cp_commit() {
    asm volatile("cp.async.commit_group;" ::: "memory");
}
template <int N> __device__ __forceinline__ void cp_wait() {
    asm volatile("cp.async.wait_group %0;" :: "n"(N) : "memory");
}
__device__ __forceinline__ void ldsm_x4(uint32_t& r0, uint32_t& r1,
                                        uint32_t& r2, uint32_t& r3, uint32_t addr) {
    asm volatile("ldmatrix.sync.aligned.m8n8.x4.shared.b16 {%0,%1,%2,%3}, [%4];"
                 : "=r"(r0), "=r"(r1), "=r"(r2), "=r"(r3) : "r"(addr));
}
__device__ __forceinline__ void mma_f16(float* d, const uint32_t* a,
                                        uint32_t b0, uint32_t b1) {
    asm volatile(
        "mma.sync.aligned.m16n8k16.row.col.f32.f16.f16.f32 "
        "{%0,%1,%2,%3}, {%4,%5,%6,%7}, {%8,%9}, {%0,%1,%2,%3};"
        : "+f"(d[0]), "+f"(d[1]), "+f"(d[2]), "+f"(d[3])
        : "r"(a[0]), "r"(a[1]), "r"(a[2]), "r"(a[3]), "r"(b0), "r"(b1));
}
__device__ __forceinline__ uint32_t packh2(float a, float b) {
    __half2 t = __halves2half2(__float2half_rn(a), __float2half_rn(b));
    return *reinterpret_cast<uint32_t*>(&t);
}
__device__ __forceinline__ int reflect_idx(int j) {
    if (j < 0) j = -j;
    else if (j >= TLEN) j = 2 * TLEN - 2 - j;
    return j;
}

// ---------------- prep 1: E/O construction (float4 fast path) ---------------
__global__ void eo_kernel(const float* __restrict__ x) {
    size_t v = (size_t)blockIdx.x * blockDim.x + threadIdx.x;   // 8-j group
    const size_t total = (size_t)BATCH * NGEMM * (KH / 8);
    if (v >= total) return;
    const int jg = (int)(v % (KH / 8));
    const int n  = (int)((v / (KH / 8)) % NGEMM);
    const int b  = (int)(v / ((size_t)(KH / 8) * NGEMM));
    const float* xb = x + (size_t)b * TLEN;
    const int j0 = jg * 8;

    float e[8], o[8];
    if (n >= 1 && n <= 2046) {
        const float* asc = xb + (size_t)n * HOP - 512 + j0;
        const float4 a0 = *reinterpret_cast<const float4*>(asc);
        const float4 a1 = *reinterpret_cast<const float4*>(asc + 4);
        const int C = n * HOP + 512 - j0;
        const float4 d0 = *reinterpret_cast<const float4*>(xb + C - 8);
        const float4 d1 = *reinterpret_cast<const float4*>(xb + C - 4);
        const float xC = xb[C];
        const float x1[8] = { a0.x, a0.y, a0.z, a0.w, a1.x, a1.y, a1.z, a1.w };
        const float x2[8] = { xC, d1.w, d1.z, d1.y, d1.x, d0.w, d0.z, d0.y };
        #pragma unroll
        for (int t = 0; t < 8; ++t) {
            e[t] = x1[t] + x2[t];
            o[t] = x1[t] - x2[t];
        }
    } else {
        #pragma unroll
        for (int t = 0; t < 8; ++t) {
            const int j = j0 + t;
            const float x1 = xb[reflect_idx(n * HOP + j - 512)];
            const float x2 = xb[reflect_idx(n * HOP + 512 - j)];
            e[t] = x1 + x2;
            o[t] = x1 - x2;
        }
    }
    if (jg == 0) { e[0] = xb[reflect_idx(n * HOP)]; o[0] = 0.f; }
    const size_t base = ((size_t)b * NGEMM + n) * KH + j0;
    *reinterpret_cast<uint4*>(g_E + base) =
        make_uint4(packh2(e[0], e[1]), packh2(e[2], e[3]),
                   packh2(e[4], e[5]), packh2(e[6], e[7]));
    *reinterpret_cast<uint4*>(g_O + base) =
        make_uint4(packh2(o[0], o[1]), packh2(o[2], o[3]),
                   packh2(o[4], o[5]), packh2(o[6], o[7]));
}

// ---------------- prep 2: basis halves (split into 2 launches) --------------
__global__ void basis_eo_kernel(const float* __restrict__ basis, int f0) {
    size_t v = (size_t)blockIdx.x * blockDim.x + threadIdx.x;   // 8-j group
    if (v >= (size_t)(FH / 2) * (KH / 8)) return;
    const int jg = (int)(v % (KH / 8));
    const int f  = f0 + (int)(v / (KH / 8));
    const int j0 = jg * 8;
    const float* bR = basis + (size_t)f * FILTER_LEN;
    const float* bI = basis + (size_t)(CUTOFF + f) * FILTER_LEN;
    float ae[8], ao[8];
    #pragma unroll
    for (int t = 0; t < 8; ++t) {
        const int j = j0 + t;
        if (j == 0) {
            ae[t] = bR[512];
            ao[t] = 0.f;
        } else {
            ae[t] = 0.5f * (bR[j] + bR[FILTER_LEN - j]);
            ao[t] = 0.5f * (bI[j] - bI[FILTER_LEN - j]);
        }
    }
    const size_t base = (size_t)f * KH + j0;
    *reinterpret_cast<uint4*>(g_AE + base) =
        make_uint4(packh2(ae[0], ae[1]), packh2(ae[2], ae[3]),
                   packh2(ae[4], ae[5]), packh2(ae[6], ae[7]));
    *reinterpret_cast<uint4*>(g_AO + base) =
        make_uint4(packh2(ao[0], ao[1]), packh2(ao[2], ao[3]),
                   packh2(ao[4], ao[5]), packh2(ao[6], ao[7]));
}

// ---------------- main: 296 CTAs = 256 persistent GEMM + 40 remainder -------
__global__ __launch_bounds__(256, 2)
void stft_mma_kernel(const float* __restrict__ x,
                     const float* __restrict__ basis,
                     const float* __restrict__ eps_p,
                     float* __restrict__ out)
{
    const int tid  = threadIdx.x;
    const int wid  = tid >> 5;
    const int lane = tid & 31;
    const int bid  = (int)blockIdx.x;

    // ======== remainder CTAs (bid >= 256): f=512 row + n=2048 col ==========
    if (bid >= NGEMM_CTAS) {
        const float eps = *eps_p;
        const int wbase = (bid - NGEMM_CTAS) * 8 + wid;
        for (int o = wbase; o < NREM; o += REMW) {
            const int b = o / (NFRAMES + 512);
            const int r = o % (NFRAMES + 512);
            int f, n;
            if (r < NFRAMES) { f = 512; n = r; }
            else             { f = r - NFRAMES; n = 2048; }
            const float* bR = basis + (size_t)f * FILTER_LEN;
            const float* bI = basis + (size_t)(f + CUTOFF) * FILTER_LEN;
            const float* xb = x + (size_t)b * TLEN;
            float aR = 0.f, aI = 0.f;
            if (n >= 1 && n <= 2047) {
                // fast path: window fully interior, float4 loads
                const float* xw = xb + (size_t)n * HOP - 512;
                #pragma unroll
                for (int s = 0; s < 8; ++s) {
                    const int k4 = (lane + 32 * s) * 4;
                    const float4 bv = *reinterpret_cast<const float4*>(bR + k4);
                    const float4 iv = *reinterpret_cast<const float4*>(bI + k4);
                    const float4 xv = *reinterpret_cast<const float4*>(xw + k4);
                    aR = fmaf(bv.x, xv.x, fmaf(bv.y, xv.y,
                         fmaf(bv.z, xv.z, fmaf(bv.w, xv.w, aR))));
                    aI = fmaf(iv.x, xv.x, fmaf(iv.y, xv.y,
                         fmaf(iv.z, xv.z, fmaf(iv.w, xv.w, aI))));
                }
            } else {
                #pragma unroll 4
                for (int k = lane; k < FILTER_LEN; k += 32) {
                    const int j = reflect_idx(n * HOP + k - 512);
                    const float xv = xb[j];
                    aR = fmaf(bR[k], xv, aR);
                    aI = fmaf(bI[k], xv, aI);
                }
            }
            #pragma unroll
            for (int s = 16; s; s >>= 1) {
                aR += __shfl_xor_sync(0xffffffffu, aR, s);
                aI += __shfl_xor_sync(0xffffffffu, aI, s);
            }
            if (lane == 0)
                out[((size_t)b * CUTOFF + f) * NFRAMES + n] =
                    sqrtf(fmaf(aR, aR, fmaf(aI, aI, eps)));
        }
        return;
    }

    // ======== persistent GEMM: 2 tiles of 128f x 128n per CTA ==============
    extern __shared__ char dsm[];
    const uint32_t sbase = smem_u32(dsm);

    const int warp_m = (wid >> 1) * 32;    // 0,32,64,96
    const int warp_n = (wid & 1) * 64;     // 0,64

    // loader: A/B each 1024 16B chunks -> 4 rounds of 256 threads
    int l_row[4], l_c16[4]; uint32_t l_soff[4];
    #pragma unroll
    for (int j = 0; j < 4; ++j) {
        int chunk = tid + j * 256;
        l_row[j] = chunk >> 3;
        l_c16[j] = chunk & 7;
        l_soff[j] = (uint32_t)l_row[j] * 128 + (uint32_t)((l_c16[j] ^ (l_row[j] & 7)) * 16);
    }

    const int lm_r = lane & 15;
    const int lm_s = lane >> 4;
    const int r4 = lane >> 2;
    const int c2 = (lane & 3) * 2;
    const float eps = *eps_p;

    for (int it = 0; it < 2; ++it) {
        const int t  = bid * 2 + it;       // tile id 0..511
        const int n0 = (t & 15) * BN;
        const int m0 = ((t >> 4) & 3) * BM;
        const int b  = t >> 6;

        const __half* aE = g_AE + (size_t)m0 * KH;
        const __half* aO = g_AO + (size_t)m0 * KH;
        const __half* bE = g_E + ((size_t)b * NGEMM + n0) * KH;
        const __half* bO = g_O + ((size_t)b * NGEMM + n0) * KH;
        float* dst = g_R + ((size_t)b * FH + m0) * NGEMM + n0;

        float acc[2][8][4];
        #pragma unroll
        for (int mt = 0; mt < 2; ++mt)
            #pragma unroll
            for (int nt = 0; nt < 8; ++nt)
                #pragma unroll
                for (int r = 0; r < 4; ++r) acc[mt][nt][r] = 0.f;

        auto load_stage = [&](int i) {
            const uint32_t st = sbase + (uint32_t)(i % NSTAGE) * STAGE;
            const __half* ap = (i < 8) ? aE : aO;
            const __half* bp = (i < 8) ? bE : bO;
            const int k0 = (i & 7) * KC;
            #pragma unroll
            for (int j = 0; j < 4; ++j) {
                cp_async16(st + SA + l_soff[j],
                           ap + (size_t)l_row[j] * KH + k0 + l_c16[j] * 8);
                cp_async16(st + SB + l_soff[j],
                           bp + (size_t)l_row[j] * KH + k0 + l_c16[j] * 8);
            }
            cp_commit();
        };

        load_stage(0);
        load_stage(1);

        for (int i = 0; i < NITER; ++i) {
            if (i + 1 < NITER) cp_wait<1>(); else cp_wait<0>();
            __syncthreads();                    // stage i ready
            if (i + 2 < NITER) load_stage(i + 2);

            if (i == 8) {
                // R phase complete: dump accs to scratch, reset for I phase
                #pragma unroll
                for (int mt = 0; mt < 2; ++mt) {
                    const int fl = warp_m + mt * 16 + r4;
                    #pragma unroll
                    for (int nt = 0; nt < 8; ++nt) {
                        const int nl = warp_n + nt * 8 + c2;
                        *reinterpret_cast<float2*>(dst + (size_t)fl * NGEMM + nl) =
                            make_float2(acc[mt][nt][0], acc[mt][nt][1]);
                        *reinterpret_cast<float2*>(dst + (size_t)(fl + 8) * NGEMM + nl) =
                            make_float2(acc[mt][nt][2], acc[mt][nt][3]);
                        acc[mt][nt][0] = 0.f; acc[mt][nt][1] = 0.f;
                        acc[mt][nt][2] = 0.f; acc[mt][nt][3] = 0.f;
                    }
                }
            }

            const uint32_t st = sbase + (uint32_t)(i % NSTAGE) * STAGE;

            #pragma unroll
            for (int ks = 0; ks < 4; ++ks) {
                const int c16 = ks * 2 + lm_s;
                uint32_t aF[2][4];
                #pragma unroll
                for (int mt = 0; mt < 2; ++mt) {
                    const int row = warp_m + mt * 16 + lm_r;
                    const uint32_t ad = st + SA + (uint32_t)row * 128
                                      + (uint32_t)((c16 ^ (row & 7)) * 16);
                    ldsm_x4(aF[mt][0], aF[mt][1], aF[mt][2], aF[mt][3], ad);
                }
                #pragma unroll
                for (int g = 0; g < 4; ++g) {
                    const int row = warp_n + g * 16 + lm_r;
                    const uint32_t bd = st + SB + (uint32_t)row * 128
                                      + (uint32_t)((c16 ^ (row & 7)) * 16);
                    uint32_t bf[4];
                    ldsm_x4(bf[0], bf[1], bf[2], bf[3], bd);
                    #pragma unroll
                    for (int sub = 0; sub < 2; ++sub) {
                        const int nt = g * 2 + sub;
                        const uint32_t b0 = sub ? bf[1] : bf[0];
                        const uint32_t b1 = sub ? bf[3] : bf[2];
                        #pragma unroll
                        for (int mt = 0; mt < 2; ++mt)
                            mma_f16(acc[mt][nt], aF[mt], b0, b1);
                    }
                }
            }
        }

        __syncthreads();   // all smem reads done before next tile's prologue

        // ---- epilogue: read back R tile, combine with I accs, magnitude ---
        #pragma unroll
        for (int mt = 0; mt < 2; ++mt) {
            #pragma unroll
            for (int nt = 0; nt < 8; ++nt) {
                const int fl = warp_m + mt * 16 + r4;
                const int nl = warp_n + nt * 8 + c2;
                const float2 r01 = *reinterpret_cast<const float2*>(
                    dst + (size_t)fl * NGEMM + nl);
                const float2 r23 = *reinterpret_cast<const float2*>(
                    dst + (size_t)(fl + 8) * NGEMM + nl);
                const int n = n0 + nl;
                float* o0 = out + ((size_t)b * CUTOFF + m0 + fl) * NFRAMES + n;
                float* o1 = out + ((size_t)b * CUTOFF + m0 + fl + 8) * NFRAMES + n;
                const float i0 = acc[mt][nt][0], i1 = acc[mt][nt][1];
                const float i2 = acc[mt][nt][2], i3 = acc[mt][nt][3];
                o0[0] = sqrtf(fmaf(r01.x, r01.x, fmaf(i0, i0, eps)));
                o0[1] = sqrtf(fmaf(r01.y, r01.y, fmaf(i1, i1, eps)));
                o1[0] = sqrtf(fmaf(r23.x, r23.x, fmaf(i2, i2, eps)));
                o1[1] = sqrtf(fmaf(r23.y, r23.y, fmaf(i3, i3, eps)));
            }
        }
    }
}

// ---------------- launch ----------------------------------------------------
extern "C" void kernel_launch(void* const* d_in, const int* in_sizes, int n_in,
                              void* d_out, int out_size)
{
    const float* x     = (const float*)d_in[0];
    const float* basis = (const float*)d_in[1];
    const float* eps   = (const float*)d_in[2];
    float* out = (float*)d_out;

    {   // launch 1
        size_t tot = (size_t)BATCH * NGEMM * (KH / 8);
        eo_kernel<<<(unsigned)((tot + 255) / 256), 256>>>(x);
    }
    {   // launches 2+3 (keeps GEMM as launch #4 for ncu)
        size_t tot = (size_t)(FH / 2) * (KH / 8);
        basis_eo_kernel<<<(unsigned)((tot + 255) / 256), 256>>>(basis, 0);
        basis_eo_kernel<<<(unsigned)((tot + 255) / 256), 256>>>(basis, FH / 2);
    }
    {   // launch 4: 296 CTAs = one full residency, persistent 2-tile GEMM
        cudaFuncSetAttribute(stft_mma_kernel,
                             cudaFuncAttributeMaxDynamicSharedMemorySize, DSMEM);
        stft_mma_kernel<<<NGEMM_CTAS + NREM_CTAS, 256, DSMEM>>>(x, basis, eps, out);
    }
}